// round 3
// baseline (speedup 1.0000x reference)
#include <cuda_runtime.h>
#include <cstdint>

// ---------------------------------------------------------------------------
// Hash-NMS v3:
//  - ONE 128-bit CAS per box (claim + max-update fused) instead of CAS+atomicMax
//  - slot = {u64 best = (conf<<32 | ~idx), u64 keytag}; 16B, 64MB table
//  - single cudaMemsetAsync clear (L2-resident), no init kernel (powf inlined)
//  - output kernel vectorized x4
// ---------------------------------------------------------------------------

#define TABLE_BITS 22
#define TABLE_SIZE (1u << TABLE_BITS)      // 4,194,304 slots
#define TABLE_MASK (TABLE_SIZE - 1u)
#define N_MAX      2100000

typedef unsigned long long u64;
typedef unsigned int       u32;

struct __align__(16) Slot {
    u64 best;    // lo 8 bytes: (conf_bits << 32) | ~index  (0 = empty)
    u64 key;     // hi 8 bytes: key | 0x80000000            (0 = empty)
};

__device__ Slot g_tab[TABLE_SIZE];
__device__ u32  g_slot[N_MAX];

__device__ __forceinline__ u32 hash_key(u32 k) {
    return (k * 0x9E3779B1u) >> (32 - TABLE_BITS);
}

// 128-bit CAS: returns previous {lo,hi}. lo = first 8 bytes in memory.
__device__ __forceinline__ void cas128(Slot* addr,
                                       u64 elo, u64 ehi,
                                       u64 dlo, u64 dhi,
                                       u64& olo, u64& ohi) {
    asm volatile(
        "{\n\t"
        ".reg .b128 e, d, o;\n\t"
        "mov.b128 e, {%2, %3};\n\t"
        "mov.b128 d, {%4, %5};\n\t"
        "atom.relaxed.gpu.global.cas.b128 o, [%6], e, d;\n\t"
        "mov.b128 {%0, %1}, o;\n\t"
        "}"
        : "=l"(olo), "=l"(ohi)
        : "l"(elo), "l"(ehi), "l"(dlo), "l"(dhi), "l"(addr)
        : "memory");
}

__global__ void insert_kernel(const float4* __restrict__ rects,
                              const float*  __restrict__ conf,
                              int n) {
    int i = blockIdx.x * blockDim.x + threadIdx.x;
    if (i >= n) return;

    float4 r = rects[i];   // cx, cy, w, h

    // Bit-identical to round-1 kernel (verified rel_err == 0.0):
    const float inv_log_alpha = 1.0f / logf(0.7f);
    int iw = (int)rintf(logf(r.z * 0.0625f) * inv_log_alpha);
    int ih = (int)rintf(logf(r.w * 0.0625f) * inv_log_alpha);
    float cw = 9.6f * powf(0.7f, (float)iw);
    float ch = 9.6f * powf(0.7f, (float)ih);
    int ix = (int)rintf(r.x / cw - 0.5f);
    int iy = (int)rintf(r.y / ch - 0.5f);

    // Compact injective key: ix,iy in [0,~580] (10b), iw,ih in [-8,4]->+16 (5b)
    int kw = min(max(iw + 16, 0), 31);
    int kh = min(max(ih + 16, 0), 31);
    u32 ex = (u32)min(max(ix, 0), 1023);
    u32 ey = (u32)min(max(iy, 0), 1023);
    u32 key = (ex << 20) | (ey << 10) | ((u32)kw << 5) | (u32)kh;

    float cf = conf[i];
    u64 dlo = ((u64)__float_as_uint(cf) << 32) | (u64)(~(u32)i);
    u64 dhi = (u64)(key | 0x80000000u);

    u32 h = hash_key(key);
    u64 elo = 0, ehi = 0;

    #pragma unroll 1
    while (true) {
        u64 olo, ohi;
        cas128(&g_tab[h], elo, ehi, dlo, dhi, olo, ohi);
        if (olo == elo && ohi == ehi) break;      // installed (claim or update)
        if (ohi == dhi) {                         // slot holds our key
            if (olo >= dlo) break;                // we lose; done
            elo = olo; ehi = ohi;                 // retry max-update
            continue;
        }
        h = (h + 1u) & TABLE_MASK;                // other key: probe on
        elo = 0; ehi = 0;
    }
    g_slot[i] = h;
}

__global__ void output_kernel(const float* __restrict__ conf,
                              float* __restrict__ out,
                              int n, int out_size) {
    int t = blockIdx.x * blockDim.x + threadIdx.x;
    int base = t * 4;
    if (base >= n) return;
    bool write_keep = (out_size >= 2 * n);

    if (base + 4 <= n) {
        float4 cf4 = *(const float4*)(conf + base);
        uint4  s4  = *(const uint4*)(g_slot + base);
        float kc[4], kp[4];
        float cfv[4] = {cf4.x, cf4.y, cf4.z, cf4.w};
        u32   sv[4]  = {s4.x, s4.y, s4.z, s4.w};
        #pragma unroll
        for (int j = 0; j < 4; j++) {
            u64 packed = ((u64)__float_as_uint(cfv[j]) << 32)
                       | (u64)(~(u32)(base + j));
            bool keep = (g_tab[sv[j]].best == packed);
            kc[j] = keep ? cfv[j] : 0.0f;
            kp[j] = keep ? 1.0f : 0.0f;
        }
        *(float4*)(out + base) = make_float4(kc[0], kc[1], kc[2], kc[3]);
        if (write_keep)
            *(float4*)(out + n + base) = make_float4(kp[0], kp[1], kp[2], kp[3]);
    } else {
        for (int i = base; i < n; i++) {
            float cf = conf[i];
            u64 packed = ((u64)__float_as_uint(cf) << 32) | (u64)(~(u32)i);
            bool keep = (g_tab[g_slot[i]].best == packed);
            out[i] = keep ? cf : 0.0f;
            if (write_keep) out[n + i] = keep ? 1.0f : 0.0f;
        }
    }
}

extern "C" void kernel_launch(void* const* d_in, const int* in_sizes, int n_in,
                              void* d_out, int out_size) {
    const float4* rects = (const float4*)d_in[0];
    const float*  conf  = (const float*) d_in[1];
    float*        out   = (float*)d_out;

    int n = in_sizes[1];          // N = 2,000,000
    if (n > N_MAX) n = N_MAX;

    const int TPB = 256;

    void* tab_ptr = nullptr;
    cudaGetSymbolAddress(&tab_ptr, g_tab);
    cudaMemsetAsync(tab_ptr, 0, (size_t)TABLE_SIZE * sizeof(Slot));

    insert_kernel<<<(n + TPB - 1) / TPB, TPB>>>(rects, conf, n);

    int nt = (n + 3) / 4;
    output_kernel<<<(nt + TPB - 1) / TPB, TPB>>>(conf, out, n, out_size);

    long long written = 2LL * (long long)n;
    if ((long long)out_size > written) {
        cudaMemsetAsync(out + written, 0,
                        ((long long)out_size - written) * sizeof(float));
    }
}

// round 4
// speedup vs baseline: 1.0326x; 1.0326x over previous
#include <cuda_runtime.h>
#include <cstdint>

// ---------------------------------------------------------------------------
// Hash-NMS v4:
//  - insert: u32 CAS claim + u64 atomicMax (48MB table), 2 boxes/thread,
//            NO per-box slot array
//  - winners recovered by linear table scan -> 256KB keep-bitmask (atomicOr)
//  - output: fully streaming (conf + bitmask -> kept_conf, keep)
//  - one cudaMemsetAsync clears table + bitmask (contiguous struct)
// ---------------------------------------------------------------------------

#define TABLE_BITS 22
#define TABLE_SIZE (1u << TABLE_BITS)      // 4,194,304 slots
#define TABLE_MASK (TABLE_SIZE - 1u)
#define N_MAX      2100000
#define BITS_WORDS ((N_MAX + 31) / 32 + 64)

typedef unsigned long long u64;
typedef unsigned int       u32;

struct GTab {
    u64 best[TABLE_SIZE];   // (conf_bits << 32) | ~index ; 0 = empty
    u32 key [TABLE_SIZE];   // key | 0x80000000 ; 0 = empty
    u32 bits[BITS_WORDS];   // keep bitmask
};
__device__ GTab g;

__device__ __forceinline__ u32 hash_key(u32 k) {
    return (k * 0x9E3779B1u) >> (32 - TABLE_BITS);
}

__device__ __forceinline__ void insert_one(const float4 r, const float cf,
                                           const u32 i) {
    // Bit-identical libdevice math (verified rel_err == 0.0 in R1-R3):
    const float inv_log_alpha = 1.0f / logf(0.7f);
    int iw = (int)rintf(logf(r.z * 0.0625f) * inv_log_alpha);
    int ih = (int)rintf(logf(r.w * 0.0625f) * inv_log_alpha);
    float cw = 9.6f * powf(0.7f, (float)iw);
    float ch = 9.6f * powf(0.7f, (float)ih);
    int ix = (int)rintf(r.x / cw - 0.5f);
    int iy = (int)rintf(r.y / ch - 0.5f);

    // Compact injective key: ix,iy in [0,~580] (10b), iw,ih in [-8,4]->+16 (5b)
    int kw = min(max(iw + 16, 0), 31);
    int kh = min(max(ih + 16, 0), 31);
    u32 ex = (u32)min(max(ix, 0), 1023);
    u32 ey = (u32)min(max(iy, 0), 1023);
    u32 key = (ex << 20) | (ey << 10) | ((u32)kw << 5) | (u32)kh;

    u32 tag = key | 0x80000000u;
    u32 h = hash_key(key);
    #pragma unroll 1
    while (true) {
        u32 prev = atomicCAS(&g.key[h], 0u, tag);
        if (prev == 0u || prev == tag) break;
        h = (h + 1u) & TABLE_MASK;
    }
    u64 packed = ((u64)__float_as_uint(cf) << 32) | (u64)(~i);
    atomicMax(&g.best[h], packed);
}

__global__ void insert_kernel(const float4* __restrict__ rects,
                              const float*  __restrict__ conf,
                              int n, int half) {
    int t = blockIdx.x * blockDim.x + threadIdx.x;
    if (t >= half) return;

    // two independent boxes per thread (ILP across the atomic chains)
    int i0 = t;
    int i1 = t + half;

    float4 r0 = rects[i0];
    float  c0 = conf[i0];
    float4 r1;
    float  c1 = 0.0f;
    bool have1 = (i1 < n);
    if (have1) { r1 = rects[i1]; c1 = conf[i1]; }

    insert_one(r0, c0, (u32)i0);
    if (have1) insert_one(r1, c1, (u32)i1);
}

// Scan best array; every nonzero entry is a bucket winner.
__global__ void scatter_kernel() {
    u32 t = blockIdx.x * blockDim.x + threadIdx.x;   // one ulonglong2 per thread
    if (t >= TABLE_SIZE / 2) return;
    ulonglong2 v = *(const ulonglong2*)(g.best + (size_t)t * 2);
    if (v.x) {
        u32 idx = ~(u32)v.x;
        atomicOr(&g.bits[idx >> 5], 1u << (idx & 31));
    }
    if (v.y) {
        u32 idx = ~(u32)v.y;
        atomicOr(&g.bits[idx >> 5], 1u << (idx & 31));
    }
}

__global__ void output_kernel(const float* __restrict__ conf,
                              float* __restrict__ out,
                              int n, int out_size) {
    int t = blockIdx.x * blockDim.x + threadIdx.x;
    int base = t * 4;
    if (base >= n) return;
    bool write_keep = (out_size >= 2 * n);

    if (base + 4 <= n) {
        float4 cf4 = *(const float4*)(conf + base);
        u32 word = g.bits[base >> 5];
        u32 sh = (u32)(base & 31);
        float kc[4], kp[4];
        float cfv[4] = {cf4.x, cf4.y, cf4.z, cf4.w};
        #pragma unroll
        for (int j = 0; j < 4; j++) {
            bool keep = (word >> (sh + j)) & 1u;
            kc[j] = keep ? cfv[j] : 0.0f;
            kp[j] = keep ? 1.0f : 0.0f;
        }
        *(float4*)(out + base) = make_float4(kc[0], kc[1], kc[2], kc[3]);
        if (write_keep)
            *(float4*)(out + n + base) = make_float4(kp[0], kp[1], kp[2], kp[3]);
    } else {
        for (int i = base; i < n; i++) {
            bool keep = (g.bits[i >> 5] >> (i & 31)) & 1u;
            float cf = conf[i];
            out[i] = keep ? cf : 0.0f;
            if (write_keep) out[n + i] = keep ? 1.0f : 0.0f;
        }
    }
}

extern "C" void kernel_launch(void* const* d_in, const int* in_sizes, int n_in,
                              void* d_out, int out_size) {
    const float4* rects = (const float4*)d_in[0];
    const float*  conf  = (const float*) d_in[1];
    float*        out   = (float*)d_out;

    int n = in_sizes[1];          // N = 2,000,000
    if (n > N_MAX) n = N_MAX;

    const int TPB = 256;

    // One clear for table (48MB) + bitmask (256KB), contiguous in struct.
    void* gptr = nullptr;
    cudaGetSymbolAddress(&gptr, g);
    cudaMemsetAsync(gptr, 0, sizeof(GTab));

    int half = (n + 1) / 2;
    insert_kernel<<<(half + TPB - 1) / TPB, TPB>>>(rects, conf, n, half);

    scatter_kernel<<<(TABLE_SIZE / 2 + TPB - 1) / TPB, TPB>>>();

    int nt = (n + 3) / 4;
    output_kernel<<<(nt + TPB - 1) / TPB, TPB>>>(conf, out, n, out_size);

    long long written = 2LL * (long long)n;
    if ((long long)out_size > written) {
        cudaMemsetAsync(out + written, 0,
                        ((long long)out_size - written) * sizeof(float));
    }
}

// round 5
// speedup vs baseline: 1.0769x; 1.0429x over previous
#include <cuda_runtime.h>
#include <cstdint>

// ---------------------------------------------------------------------------
// Hash-NMS v5 — perfect (collision-free) direct-mapped table:
//   slot = X * 1945 + Y,  X = base[iw+8] + ix,  Y = base[ih+8] + iy
//   (iw,ih in [-8,4] for w,h in [4,256]; per-scale ix capacity sums to 1945;
//    1945^2 = 3,783,025 < 4M slots = 32MB u64)
//   -> insert is ONE fire-and-forget atomicMax (RED), no CAS/probe/key array.
//   powf via 13-entry per-block smem table (same libdevice bits).
// ---------------------------------------------------------------------------

#define TABLE_SIZE 3783025u
#define TABLE_PAD  3784704u          // padded for vector scan (div by 2)
#define N_MAX      2100000
#define BITS_WORDS ((N_MAX + 31) / 32 + 64)
#define XDIM       1945

typedef unsigned long long u64;
typedef unsigned int       u32;

struct GTab {
    u64 best[TABLE_PAD];    // (conf_bits << 32) | ~index ; 0 = empty
    u32 bits[BITS_WORDS];   // keep bitmask
};
__device__ GTab g;

// prefix sums of per-scale ix capacities {11,14,19,26,36,50,71,100,142,201,286,408,581}
__constant__ int c_base[14] =
    {0, 11, 25, 44, 70, 106, 156, 227, 327, 469, 670, 956, 1364, 1945};

__global__ void insert_kernel(const float4* __restrict__ rects,
                              const float*  __restrict__ conf,
                              int n) {
    __shared__ float s_cw[13];
    int tid = threadIdx.x;
    if (tid < 13)
        s_cw[tid] = 9.6f * powf(0.7f, (float)(tid - 8));   // same libdevice powf
    __syncthreads();

    int i = blockIdx.x * blockDim.x + tid;
    if (i >= n) return;

    float4 r = rects[i];   // cx, cy, w, h

    // Bit-identical libdevice math (verified rel_err == 0.0 in R1-R4):
    const float inv_log_alpha = 1.0f / logf(0.7f);
    int iw = (int)rintf(logf(r.z * 0.0625f) * inv_log_alpha);
    int ih = (int)rintf(logf(r.w * 0.0625f) * inv_log_alpha);

    int kw = min(max(iw + 8, 0), 12);
    int kh = min(max(ih + 8, 0), 12);
    float cw = s_cw[kw];
    float ch = s_cw[kh];

    int ix = (int)rintf(r.x / cw - 0.5f);
    int iy = (int)rintf(r.y / ch - 0.5f);

    // Perfect slot: X/Y ranges per scale bucket are disjoint by construction.
    int bx = c_base[kw], bx1 = c_base[kw + 1];
    int by = c_base[kh], by1 = c_base[kh + 1];
    int X = min(max(bx + ix, bx), bx1 - 1);   // clamps never fire for valid data
    int Y = min(max(by + iy, by), by1 - 1);
    u32 slot = (u32)(X * XDIM + Y);

    float cf = conf[i];
    u64 packed = ((u64)__float_as_uint(cf) << 32) | (u64)(~(u32)i);
    atomicMax(&g.best[slot], packed);          // return unused -> RED
}

// Scan best array; every nonzero entry is a bucket winner.
__global__ void scatter_kernel() {
    u32 t = blockIdx.x * blockDim.x + threadIdx.x;   // one ulonglong2 / thread
    if (t >= TABLE_PAD / 2) return;
    ulonglong2 v = *(const ulonglong2*)(g.best + (size_t)t * 2);
    if (v.x) {
        u32 idx = ~(u32)v.x;
        atomicOr(&g.bits[idx >> 5], 1u << (idx & 31));
    }
    if (v.y) {
        u32 idx = ~(u32)v.y;
        atomicOr(&g.bits[idx >> 5], 1u << (idx & 31));
    }
}

__global__ void output_kernel(const float* __restrict__ conf,
                              float* __restrict__ out,
                              int n, int out_size) {
    int t = blockIdx.x * blockDim.x + threadIdx.x;
    int base = t * 4;
    if (base >= n) return;
    bool write_keep = (out_size >= 2 * n);

    if (base + 4 <= n) {
        float4 cf4 = *(const float4*)(conf + base);
        u32 word = g.bits[base >> 5];
        u32 sh = (u32)(base & 31);
        float kc[4], kp[4];
        float cfv[4] = {cf4.x, cf4.y, cf4.z, cf4.w};
        #pragma unroll
        for (int j = 0; j < 4; j++) {
            bool keep = (word >> (sh + j)) & 1u;
            kc[j] = keep ? cfv[j] : 0.0f;
            kp[j] = keep ? 1.0f : 0.0f;
        }
        *(float4*)(out + base) = make_float4(kc[0], kc[1], kc[2], kc[3]);
        if (write_keep)
            *(float4*)(out + n + base) = make_float4(kp[0], kp[1], kp[2], kp[3]);
    } else {
        for (int i = base; i < n; i++) {
            bool keep = (g.bits[i >> 5] >> (i & 31)) & 1u;
            float cf = conf[i];
            out[i] = keep ? cf : 0.0f;
            if (write_keep) out[n + i] = keep ? 1.0f : 0.0f;
        }
    }
}

extern "C" void kernel_launch(void* const* d_in, const int* in_sizes, int n_in,
                              void* d_out, int out_size) {
    const float4* rects = (const float4*)d_in[0];
    const float*  conf  = (const float*) d_in[1];
    float*        out   = (float*)d_out;

    int n = in_sizes[1];          // N = 2,000,000
    if (n > N_MAX) n = N_MAX;

    const int TPB = 256;

    // One clear for table (32MB) + bitmask, contiguous in struct.
    void* gptr = nullptr;
    cudaGetSymbolAddress(&gptr, g);
    cudaMemsetAsync(gptr, 0, sizeof(GTab));

    insert_kernel<<<(n + TPB - 1) / TPB, TPB>>>(rects, conf, n);

    scatter_kernel<<<(TABLE_PAD / 2 + TPB - 1) / TPB, TPB>>>();

    int nt = (n + 3) / 4;
    output_kernel<<<(nt + TPB - 1) / TPB, TPB>>>(conf, out, n, out_size);

    long long written = 2LL * (long long)n;
    if ((long long)out_size > written) {
        cudaMemsetAsync(out + written, 0,
                        ((long long)out_size - written) * sizeof(float));
    }
}